// round 1
// baseline (speedup 1.0000x reference)
#include <cuda_runtime.h>
#include <math.h>
#include <stdint.h>

#define DIMF 128
#define N_LEGO 50000
#define N_POINT 100000
#define NE_LL 500000
#define NE_PP 400000
#define NE_LP 500000
#define NE_PL 500000
#define NEG_INF_KEY 0x007FFFFFu

// ---------------- scratch (static device allocations; no cudaMalloc) ----------------
__device__ float    g_xl[N_LEGO * DIMF];
__device__ float    g_xp[N_POINT * DIMF];
__device__ float    g_la[N_LEGO * DIMF];
__device__ float    g_pa[N_POINT * DIMF];
__device__ float    g_q[N_LEGO * DIMF];
__device__ float    g_k[N_LEGO * DIMF];
__device__ float    g_v[N_LEGO * DIMF];
__device__ float    g_hs[N_POINT * DIMF];
__device__ float    g_hd[N_POINT * DIMF];
__device__ float    g_ss[N_POINT];
__device__ float    g_sd[N_POINT];
__device__ float    g_escore[NE_LL];
__device__ unsigned g_mkey[N_POINT];
__device__ float    g_dsum[N_POINT];
__device__ float    g_P[N_POINT * 512];
__device__ float    g_Q[N_POINT * 512];
__device__ float    g_H[204800000];       // NE_PP * 512
__device__ float    g_M[51200000];        // NE_PP * 128
__device__ unsigned g_emax[N_POINT * DIMF];

// ---------------- helpers ----------------
__device__ __forceinline__ unsigned fkey(float f) {
    unsigned u = __float_as_uint(f);
    return (u & 0x80000000u) ? ~u : (u | 0x80000000u);
}
__device__ __forceinline__ float fdecode(unsigned kk) {
    unsigned u = (kk & 0x80000000u) ? (kk ^ 0x80000000u) : ~kk;
    return __uint_as_float(u);
}

// ---------------- SGEMM: C[M,N] = A[M,K] @ B[K,N] (+ bias) ----------------
// 128x128 block tile, BK=8, 256 threads, 8x8 microtile.
__global__ __launch_bounds__(256) void sgemm_kernel(
    const float* __restrict__ A, const float* __restrict__ B,
    const float* __restrict__ bias, float* __restrict__ C,
    int M, int N, int K)
{
    __shared__ float As[8][128];
    __shared__ float Bs[8][128];
    int tid = threadIdx.x;
    int block_row = blockIdx.y, block_col = blockIdx.x;
    int tr = tid >> 4, tc = tid & 15;

    int a_row = tid >> 1;
    int a_col = (tid & 1) * 4;
    int b_row = tid >> 5;
    int b_col = (tid & 31) * 4;

    int gArow = block_row * 128 + a_row;
    bool a_ok = (gArow < M);
    const float* Aptr = A + (size_t)(a_ok ? gArow : 0) * K + a_col;
    const float* Bptr = B + (size_t)b_row * N + block_col * 128 + b_col;

    float acc[8][8];
#pragma unroll
    for (int i = 0; i < 8; i++)
#pragma unroll
        for (int j = 0; j < 8; j++) acc[i][j] = 0.f;

    for (int kt = 0; kt < K; kt += 8) {
        float4 av = a_ok ? *(const float4*)(Aptr + kt) : make_float4(0.f, 0.f, 0.f, 0.f);
        As[a_col + 0][a_row] = av.x; As[a_col + 1][a_row] = av.y;
        As[a_col + 2][a_row] = av.z; As[a_col + 3][a_row] = av.w;
        float4 bv = *(const float4*)(Bptr + (size_t)kt * N);
        *(float4*)&Bs[b_row][b_col] = bv;
        __syncthreads();
#pragma unroll
        for (int kk = 0; kk < 8; kk++) {
            float4 a0 = *(const float4*)&As[kk][tr * 4];
            float4 a1 = *(const float4*)&As[kk][64 + tr * 4];
            float4 b0 = *(const float4*)&Bs[kk][tc * 4];
            float4 b1 = *(const float4*)&Bs[kk][64 + tc * 4];
            float ar[8] = {a0.x, a0.y, a0.z, a0.w, a1.x, a1.y, a1.z, a1.w};
            float br[8] = {b0.x, b0.y, b0.z, b0.w, b1.x, b1.y, b1.z, b1.w};
#pragma unroll
            for (int i = 0; i < 8; i++)
#pragma unroll
                for (int j = 0; j < 8; j++) acc[i][j] = fmaf(ar[i], br[j], acc[i][j]);
        }
        __syncthreads();
    }

#pragma unroll
    for (int i = 0; i < 8; i++) {
        int r_local = (i < 4) ? (tr * 4 + i) : (64 + tr * 4 + (i - 4));
        int r = block_row * 128 + r_local;
        if (r >= M) continue;
#pragma unroll
        for (int jh = 0; jh < 2; jh++) {
            int c_local = (jh == 0) ? (tc * 4) : (64 + tc * 4);
            int c = block_col * 128 + c_local;
            float4 v;
            v.x = acc[i][jh * 4 + 0]; v.y = acc[i][jh * 4 + 1];
            v.z = acc[i][jh * 4 + 2]; v.w = acc[i][jh * 4 + 3];
            if (bias) {
                float4 bb = *(const float4*)(bias + c);
                v.x += bb.x; v.y += bb.y; v.z += bb.z; v.w += bb.w;
            }
            *(float4*)(C + (size_t)r * N + c) = v;
        }
    }
}

// ---------------- graph kernels ----------------
__global__ void reset_softmax_kernel(unsigned* mkey, float* dsum, int n) {
    int i = blockIdx.x * blockDim.x + threadIdx.x;
    if (i < n) { mkey[i] = NEG_INF_KEY; dsum[i] = 0.f; }
}

__global__ void fill_u32_kernel(unsigned* p, unsigned val, int n) {
    int i = blockIdx.x * blockDim.x + threadIdx.x;
    if (i < n) p[i] = val;
}

// one warp per edge: score = dot(q[dst], k[src]) * scale ; atomicMax into mkey
__global__ void trans_score_kernel(
    const float* __restrict__ q, const float* __restrict__ k,
    const int* __restrict__ src, const int* __restrict__ dst,
    float* __restrict__ score, unsigned* __restrict__ mkey, int E, float scale)
{
    int idx = blockIdx.x * blockDim.x + threadIdx.x;
    int e = idx >> 5, lane = idx & 31;
    if (e >= E) return;
    int d = dst[e], s0 = src[e];
    float4 qv = *(const float4*)(q + (size_t)d * DIMF + lane * 4);
    float4 kv = *(const float4*)(k + (size_t)s0 * DIMF + lane * 4);
    float s = qv.x * kv.x + qv.y * kv.y + qv.z * kv.z + qv.w * kv.w;
#pragma unroll
    for (int o = 16; o; o >>= 1) s += __shfl_xor_sync(0xffffffffu, s, o);
    if (lane == 0) {
        s *= scale;
        score[e] = s;
        atomicMax(mkey + d, fkey(s));
    }
}

// one warp per node: out[n] = dot(h[n,:], avec)
__global__ void node_dot_kernel(const float* __restrict__ h, const float* __restrict__ avec,
                                float* __restrict__ out, int n)
{
    int idx = blockIdx.x * blockDim.x + threadIdx.x;
    int i = idx >> 5, lane = idx & 31;
    if (i >= n) return;
    float4 hv = *(const float4*)(h + (size_t)i * DIMF + lane * 4);
    float4 av = *(const float4*)(avec + lane * 4);
    float s = hv.x * av.x + hv.y * av.y + hv.z * av.z + hv.w * av.w;
#pragma unroll
    for (int o = 16; o; o >>= 1) s += __shfl_xor_sync(0xffffffffu, s, o);
    if (lane == 0) out[i] = s;
}

__global__ void gat_score_kernel(const float* __restrict__ ss, const float* __restrict__ sd,
                                 const int* __restrict__ src, const int* __restrict__ dst,
                                 float* __restrict__ score, unsigned* __restrict__ mkey, int E)
{
    int e = blockIdx.x * blockDim.x + threadIdx.x;
    if (e >= E) return;
    float s = ss[src[e]] + sd[dst[e]];
    s = (s > 0.f) ? s : 0.2f * s;
    score[e] = s;
    atomicMax(mkey + dst[e], fkey(s));
}

__global__ void expsum_kernel(float* __restrict__ score, const unsigned* __restrict__ mkey,
                              float* __restrict__ dsum, const int* __restrict__ dst, int E)
{
    int e = blockIdx.x * blockDim.x + threadIdx.x;
    if (e >= E) return;
    int d = dst[e];
    float m = fdecode(mkey[d]);
    if (!isfinite(m)) m = 0.f;
    float ex = expf(score[e] - m);
    score[e] = ex;
    atomicAdd(dsum + d, ex);
}

// one warp per edge: out[dst,:] += (score[e]/dsum[dst]) * v[src,:]
__global__ void aggregate_kernel(const float* __restrict__ score, const float* __restrict__ dsum,
                                 const float* __restrict__ v,
                                 const int* __restrict__ src, const int* __restrict__ dst,
                                 float* __restrict__ out, int E)
{
    int idx = blockIdx.x * blockDim.x + threadIdx.x;
    int e = idx >> 5, lane = idx & 31;
    if (e >= E) return;
    int d = dst[e], s0 = src[e];
    float w = score[e] / (dsum[d] + 1e-16f);
    float4 vv = *(const float4*)(v + (size_t)s0 * DIMF + lane * 4);
    float* op = out + (size_t)d * DIMF + lane * 4;
    atomicAdd(op + 0, w * vv.x);
    atomicAdd(op + 1, w * vv.y);
    atomicAdd(op + 2, w * vv.z);
    atomicAdd(op + 3, w * vv.w);
}

__global__ void bias_add_kernel(float* __restrict__ out, const float* __restrict__ b, int n) {
    int i = blockIdx.x * blockDim.x + threadIdx.x;   // n*32 float4 slots
    if (i >= n * 32) return;
    int f = (i & 31) * 4;
    float4 bv = *(const float4*)(b + f);
    float4 ov = *(float4*)(out + (size_t)i * 4);
    ov.x += bv.x; ov.y += bv.y; ov.z += bv.z; ov.w += bv.w;
    *(float4*)(out + (size_t)i * 4) = ov;
}

// one warp per edge: H[e,:] = relu(P[dst] - Q[dst] + Q[src] + b1)   (512 wide)
__global__ void edge_h_kernel(const float* __restrict__ P, const float* __restrict__ Q,
                              const float* __restrict__ b1,
                              const int* __restrict__ src, const int* __restrict__ dst,
                              float* __restrict__ H, int E)
{
    int idx = blockIdx.x * blockDim.x + threadIdx.x;
    int e = idx >> 5, lane = idx & 31;
    if (e >= E) return;
    int d = dst[e], s0 = src[e];
    const float* Pd = P + (size_t)d * 512;
    const float* Qd = Q + (size_t)d * 512;
    const float* Qs = Q + (size_t)s0 * 512;
    float* He = H + (size_t)e * 512;
#pragma unroll
    for (int t = 0; t < 4; t++) {
        int c = t * 128 + lane * 4;
        float4 p  = *(const float4*)(Pd + c);
        float4 qd = *(const float4*)(Qd + c);
        float4 qs = *(const float4*)(Qs + c);
        float4 bb = *(const float4*)(b1 + c);
        float4 h;
        h.x = fmaxf(p.x - qd.x + qs.x + bb.x, 0.f);
        h.y = fmaxf(p.y - qd.y + qs.y + bb.y, 0.f);
        h.z = fmaxf(p.z - qd.z + qs.z + bb.z, 0.f);
        h.w = fmaxf(p.w - qd.w + qs.w + bb.w, 0.f);
        *(float4*)(He + c) = h;
    }
}

// one warp per edge: emax[dst,f] = max(emax, M[e,f]) via monotone-uint atomicMax
__global__ void scatter_max_kernel(const float* __restrict__ Mb, const int* __restrict__ dst,
                                   unsigned* __restrict__ emax, int E)
{
    int idx = blockIdx.x * blockDim.x + threadIdx.x;
    int e = idx >> 5, lane = idx & 31;
    if (e >= E) return;
    int d = dst[e];
    float4 mv = *(const float4*)(Mb + (size_t)e * DIMF + lane * 4);
    unsigned* ep = emax + (size_t)d * DIMF + lane * 4;
    atomicMax(ep + 0, fkey(mv.x));
    atomicMax(ep + 1, fkey(mv.y));
    atomicMax(ep + 2, fkey(mv.z));
    atomicMax(ep + 3, fkey(mv.w));
}

__global__ void finalize_max_kernel(const unsigned* __restrict__ emax, float* __restrict__ out, int total) {
    int i = blockIdx.x * blockDim.x + threadIdx.x;
    if (i >= total) return;
    float v = fdecode(emax[i]);
    out[i] = isfinite(v) ? v : 0.f;
}

// ---------------- host orchestration ----------------
static inline int div_up(int a, int b) { return (a + b - 1) / b; }

static void sgemm(const float* A, const float* B, const float* bias, float* C, int M, int N, int K) {
    dim3 grid(N / 128, div_up(M, 128));
    sgemm_kernel<<<grid, 256>>>(A, B, bias, C, M, N, K);
}

struct Scratch {
    float *xl, *xp, *la, *pa, *q, *k, *v, *hs, *hd, *ss, *sd, *escore, *dsum, *P, *Q, *H, *M;
    unsigned *mkey, *emax;
};

static void run_trans(const Scratch& S, const float* x, int n,
                      const int* src, const int* dst, int E,
                      const float* Wq, const float* bq, const float* Wk, const float* bk,
                      const float* Wv, const float* bv, const float* Ws, const float* bs,
                      float* out)
{
    sgemm(x, Ws, bs, out, n, DIMF, DIMF);           // skip: out = x@Ws + bs
    sgemm(x, Wq, bq, S.q, n, DIMF, DIMF);
    sgemm(x, Wk, bk, S.k, n, DIMF, DIMF);
    sgemm(x, Wv, bv, S.v, n, DIMF, DIMF);
    reset_softmax_kernel<<<div_up(n, 256), 256>>>(S.mkey, S.dsum, n);
    float scale = 1.f / sqrtf((float)DIMF);
    trans_score_kernel<<<div_up(E * 32, 256), 256>>>(S.q, S.k, src, dst, S.escore, S.mkey, E, scale);
    expsum_kernel<<<div_up(E, 256), 256>>>(S.escore, S.mkey, S.dsum, dst, E);
    aggregate_kernel<<<div_up(E * 32, 256), 256>>>(S.escore, S.dsum, S.v, src, dst, out, E);
}

static void run_gat(const Scratch& S, const float* xs, int ns, const float* xd, int nd,
                    const int* src, const int* dst, int E,
                    const float* W, const float* a_src, const float* a_dst, const float* b,
                    float* out)   // accumulates into out
{
    sgemm(xs, W, nullptr, S.hs, ns, DIMF, DIMF);
    sgemm(xd, W, nullptr, S.hd, nd, DIMF, DIMF);
    node_dot_kernel<<<div_up(ns * 32, 256), 256>>>(S.hs, a_src, S.ss, ns);
    node_dot_kernel<<<div_up(nd * 32, 256), 256>>>(S.hd, a_dst, S.sd, nd);
    reset_softmax_kernel<<<div_up(nd, 256), 256>>>(S.mkey, S.dsum, nd);
    gat_score_kernel<<<div_up(E, 256), 256>>>(S.ss, S.sd, src, dst, S.escore, S.mkey, E);
    expsum_kernel<<<div_up(E, 256), 256>>>(S.escore, S.mkey, S.dsum, dst, E);
    aggregate_kernel<<<div_up(E * 32, 256), 256>>>(S.escore, S.dsum, S.hs, src, dst, out, E);
    bias_add_kernel<<<div_up(nd * 32, 256), 256>>>(out, b, nd);
}

static void run_edge(const Scratch& S, const float* x, int n,
                     const int* src, const int* dst, int E,
                     const float* W1, const float* b1, const float* W2, const float* b2,
                     float* out)   // stores out (overwrite)
{
    const float* W1a = W1;              // first 128 rows  (applies to x_i)
    const float* W1b = W1 + 128 * 512;  // second 128 rows (applies to x_j - x_i)
    sgemm(x, W1a, nullptr, S.P, n, 512, DIMF);
    sgemm(x, W1b, nullptr, S.Q, n, 512, DIMF);
    edge_h_kernel<<<div_up(E * 32, 256), 256>>>(S.P, S.Q, b1, src, dst, S.H, E);
    sgemm(S.H, W2, b2, S.M, E, DIMF, 512);
    fill_u32_kernel<<<div_up(n * DIMF, 256), 256>>>(S.emax, NEG_INF_KEY, n * DIMF);
    scatter_max_kernel<<<div_up(E * 32, 256), 256>>>(S.M, dst, S.emax, E);
    finalize_max_kernel<<<div_up(n * DIMF, 256), 256>>>(S.emax, out, n * DIMF);
}

extern "C" void kernel_launch(void* const* d_in, const int* in_sizes, int n_in,
                              void* d_out, int out_size)
{
    const float* x_lego  = (const float*)d_in[0];
    const float* x_point = (const float*)d_in[1];
    const float* tWq = (const float*)d_in[2];
    const float* tbq = (const float*)d_in[3];
    const float* tWk = (const float*)d_in[4];
    const float* tbk = (const float*)d_in[5];
    const float* tWv = (const float*)d_in[6];
    const float* tbv = (const float*)d_in[7];
    const float* tWs = (const float*)d_in[8];
    const float* tbs = (const float*)d_in[9];
    const float* eW1 = (const float*)d_in[10];
    const float* eb1 = (const float*)d_in[11];
    const float* eW2 = (const float*)d_in[12];
    const float* eb2 = (const float*)d_in[13];
    const float* gW  = (const float*)d_in[14];
    const float* gAs = (const float*)d_in[15];
    const float* gAd = (const float*)d_in[16];
    const float* gb  = (const float*)d_in[17];
    const int* ll_src = (const int*)d_in[18];
    const int* ll_dst = (const int*)d_in[19];
    const int* pp_src = (const int*)d_in[20];
    const int* pp_dst = (const int*)d_in[21];
    const int* lp_src = (const int*)d_in[22];
    const int* lp_dst = (const int*)d_in[23];
    const int* pl_src = (const int*)d_in[24];
    const int* pl_dst = (const int*)d_in[25];

    Scratch S;
    cudaGetSymbolAddress((void**)&S.xl, g_xl);
    cudaGetSymbolAddress((void**)&S.xp, g_xp);
    cudaGetSymbolAddress((void**)&S.la, g_la);
    cudaGetSymbolAddress((void**)&S.pa, g_pa);
    cudaGetSymbolAddress((void**)&S.q,  g_q);
    cudaGetSymbolAddress((void**)&S.k,  g_k);
    cudaGetSymbolAddress((void**)&S.v,  g_v);
    cudaGetSymbolAddress((void**)&S.hs, g_hs);
    cudaGetSymbolAddress((void**)&S.hd, g_hd);
    cudaGetSymbolAddress((void**)&S.ss, g_ss);
    cudaGetSymbolAddress((void**)&S.sd, g_sd);
    cudaGetSymbolAddress((void**)&S.escore, g_escore);
    cudaGetSymbolAddress((void**)&S.dsum, g_dsum);
    cudaGetSymbolAddress((void**)&S.P, g_P);
    cudaGetSymbolAddress((void**)&S.Q, g_Q);
    cudaGetSymbolAddress((void**)&S.H, g_H);
    cudaGetSymbolAddress((void**)&S.M, g_M);
    cudaGetSymbolAddress((void**)&S.mkey, g_mkey);
    cudaGetSymbolAddress((void**)&S.emax, g_emax);

    cudaMemcpyAsync(S.xl, x_lego,  (size_t)N_LEGO * DIMF * sizeof(float),  cudaMemcpyDeviceToDevice);
    cudaMemcpyAsync(S.xp, x_point, (size_t)N_POINT * DIMF * sizeof(float), cudaMemcpyDeviceToDevice);

    for (int layer = 0; layer < 2; layer++) {
        int iA = 2 * layer, iB = 2 * layer + 1;
        int i_lp = 2 * layer, i_pl = 2 * layer + 1;

        // ---- conv A: lego_a = trans(x_lego) + gat(point->lego) ----
        run_trans(S, S.xl, N_LEGO, ll_src, ll_dst, NE_LL,
                  tWq + iA * DIMF * DIMF, tbq + iA * DIMF,
                  tWk + iA * DIMF * DIMF, tbk + iA * DIMF,
                  tWv + iA * DIMF * DIMF, tbv + iA * DIMF,
                  tWs + iA * DIMF * DIMF, tbs + iA * DIMF,
                  S.la);
        run_gat(S, S.xp, N_POINT, S.xl, N_LEGO, pl_src, pl_dst, NE_PL,
                gW + i_pl * DIMF * DIMF, gAs + i_pl * DIMF, gAd + i_pl * DIMF, gb + i_pl * DIMF,
                S.la);

        // ---- conv A: point_a = edge(x_point) + gat(lego->point) ----
        run_edge(S, S.xp, N_POINT, pp_src, pp_dst, NE_PP,
                 eW1 + (size_t)iA * 256 * 512, eb1 + iA * 512,
                 eW2 + (size_t)iA * 512 * DIMF, eb2 + iA * DIMF,
                 S.pa);
        run_gat(S, S.xl, N_LEGO, S.xp, N_POINT, lp_src, lp_dst, NE_LP,
                gW + i_lp * DIMF * DIMF, gAs + i_lp * DIMF, gAd + i_lp * DIMF, gb + i_lp * DIMF,
                S.pa);

        // ---- conv B: x_lego = trans(lego_a); x_point = edge(point_a) ----
        run_trans(S, S.la, N_LEGO, ll_src, ll_dst, NE_LL,
                  tWq + iB * DIMF * DIMF, tbq + iB * DIMF,
                  tWk + iB * DIMF * DIMF, tbk + iB * DIMF,
                  tWv + iB * DIMF * DIMF, tbv + iB * DIMF,
                  tWs + iB * DIMF * DIMF, tbs + iB * DIMF,
                  S.xl);
        run_edge(S, S.pa, N_POINT, pp_src, pp_dst, NE_PP,
                 eW1 + (size_t)iB * 256 * 512, eb1 + iB * 512,
                 eW2 + (size_t)iB * 512 * DIMF, eb2 + iB * DIMF,
                 S.xp);
    }

    float* out = (float*)d_out;
    cudaMemcpyAsync(out, S.xl, (size_t)N_LEGO * DIMF * sizeof(float), cudaMemcpyDeviceToDevice);
    cudaMemcpyAsync(out + (size_t)N_LEGO * DIMF, S.xp, (size_t)N_POINT * DIMF * sizeof(float),
                    cudaMemcpyDeviceToDevice);
}

// round 3
// speedup vs baseline: 1.2471x; 1.2471x over previous
#include <cuda_runtime.h>
#include <math.h>
#include <stdint.h>

#define DIMF 128
#define N_LEGO 50000
#define N_POINT 100000
#define NE_LL 500000
#define NE_PP 400000
#define NE_LP 500000
#define NE_PL 500000
#define NEG_INF_KEY 0x007FFFFFu

// ---------------- scratch (static device allocations; no cudaMalloc) ----------------
__device__ float    g_xl[N_LEGO * DIMF];
__device__ float    g_xp[N_POINT * DIMF];
__device__ float    g_la[N_LEGO * DIMF];
__device__ float    g_pa[N_POINT * DIMF];
__device__ float    g_q[N_LEGO * DIMF];
__device__ float    g_k[N_LEGO * DIMF];
__device__ float    g_v[N_LEGO * DIMF];
__device__ float    g_hs[N_POINT * DIMF];
__device__ float    g_hd[N_POINT * DIMF];
__device__ float    g_ss[N_POINT];
__device__ float    g_sd[N_POINT];
__device__ float    g_escore[NE_LL];
__device__ unsigned g_mkey[N_POINT];
__device__ float    g_dsum[N_POINT];
__device__ float    g_P[N_POINT * 512];
__device__ float    g_Q[N_POINT * 512];
__device__ float    g_H[204800000];       // NE_PP * 512
__device__ float    g_M[51200000];        // NE_PP * 128
__device__ unsigned g_emax[N_POINT * DIMF];

// ---------------- helpers ----------------
__device__ __forceinline__ unsigned fkey(float f) {
    unsigned u = __float_as_uint(f);
    return (u & 0x80000000u) ? ~u : (u | 0x80000000u);
}
__device__ __forceinline__ float fdecode(unsigned kk) {
    unsigned u = (kk & 0x80000000u) ? (kk ^ 0x80000000u) : ~kk;
    return __uint_as_float(u);
}
__device__ __forceinline__ float to_tf32(float x) {
    float r;
    asm("cvt.rna.tf32.f32 %0, %1;" : "=f"(r) : "f"(x));
    return r;
}
__device__ __forceinline__ void tf32_split(float v, uint32_t& hi, uint32_t& lo) {
    float h = to_tf32(v);
    float l = to_tf32(v - h);
    hi = __float_as_uint(h);
    lo = __float_as_uint(l);
}
__device__ __forceinline__ void cp_async16(void* dst, const void* src, int bytes) {
    uint32_t d = (uint32_t)__cvta_generic_to_shared(dst);
    asm volatile("cp.async.ca.shared.global [%0], [%1], 16, %2;\n"
                 :: "r"(d), "l"(src), "r"(bytes));
}

// ---------------- 3xTF32 tensor-core GEMM: C[M,N] = A[M,K] @ B[K,N] (+bias) ----------------
// BM=128, BN=128, BK=32, 256 threads = 8 warps (4 in M x 2 in N).
// Warp tile 32x64 = 2 m16 x 8 n8 tiles, mma.m16n8k8.tf32, hi/lo split (3 MMAs).
// Double-buffered smem fed by cp.async.
#define BM 128
#define BN 128
#define BK 32
#define AS_STRIDE 36     // As[m][k] : [128][36]  -> a-frag banks 4g+t (conflict-free)
#define BS_STRIDE 136    // Bs[k][n] : [32][136]  -> b-frag banks 8t+g (conflict-free)
#define SMEM_FLOATS (2 * BM * AS_STRIDE + 2 * BK * BS_STRIDE)

#define MMA_TF32(accv, a0, a1, a2, a3, b0, b1)                                     \
    asm("mma.sync.aligned.m16n8k8.row.col.f32.tf32.tf32.f32 "                      \
        "{%0,%1,%2,%3}, {%4,%5,%6,%7}, {%8,%9}, {%0,%1,%2,%3};"                    \
        : "+f"(accv[0]), "+f"(accv[1]), "+f"(accv[2]), "+f"(accv[3])               \
        : "r"(a0), "r"(a1), "r"(a2), "r"(a3), "r"(b0), "r"(b1))

__global__ __launch_bounds__(256, 2) void mma3_sgemm_kernel(
    const float* __restrict__ A, const float* __restrict__ B,
    const float* __restrict__ bias, float* __restrict__ C,
    int M, int N, int K)
{
    extern __shared__ float smem[];
    float (*As)[BM][AS_STRIDE] = (float (*)[BM][AS_STRIDE])smem;
    float (*Bs)[BK][BS_STRIDE] = (float (*)[BK][BS_STRIDE])(smem + 2 * BM * AS_STRIDE);

    const int tid  = threadIdx.x;
    const int warp = tid >> 5, lane = tid & 31;
    const int g = lane >> 2, t = lane & 3;
    const int warp_m = warp & 3, warp_n = warp >> 2;
    const int m_base = blockIdx.y * BM;
    const int n_base = blockIdx.x * BN;
    const int wm = warp_m * 32;
    const int wn = warp_n * 64;

    float acc[2][8][4];
#pragma unroll
    for (int i = 0; i < 2; i++)
#pragma unroll
        for (int j = 0; j < 8; j++)
#pragma unroll
            for (int c = 0; c < 4; c++) acc[i][j][c] = 0.f;

    // A tile: 128 rows x 32 cols = 1024 float4 slots; idx: row=idx>>3, c4=(idx&7)*4
    // B tile: 32 rows x 128 cols = 1024 float4 slots; idx: row=idx>>5, c4=(idx&31)*4
#define ISSUE_TILES(k0, st)                                                        \
    {                                                                              \
        _Pragma("unroll")                                                          \
        for (int i = 0; i < 4; i++) {                                              \
            int idx = tid + i * 256;                                               \
            int row = idx >> 3, c4 = (idx & 7) * 4;                                \
            int gr = m_base + row;                                                 \
            cp_async16(&As[st][row][c4], A + (size_t)gr * K + (k0) + c4,           \
                       (gr < M) ? 16 : 0);                                         \
        }                                                                          \
        _Pragma("unroll")                                                          \
        for (int i = 0; i < 4; i++) {                                              \
            int idx = tid + i * 256;                                               \
            int row = idx >> 5, c4 = (idx & 31) * 4;                               \
            cp_async16(&Bs[st][row][c4],                                           \
                       B + (size_t)((k0) + row) * N + n_base + c4, 16);            \
        }                                                                          \
        asm volatile("cp.async.commit_group;\n" ::);                               \
    }

    ISSUE_TILES(0, 0);

    int stage = 0;
    for (int kt = 0; kt < K; kt += BK, stage ^= 1) {
        const bool more = (kt + BK) < K;
        if (more) ISSUE_TILES(kt + BK, stage ^ 1);
        if (more) asm volatile("cp.async.wait_group 1;\n" ::);
        else      asm volatile("cp.async.wait_group 0;\n" ::);
        __syncthreads();

#pragma unroll
        for (int ks = 0; ks < 4; ks++) {
            const int k0 = ks * 8;
            uint32_t afh[2][4], afl[2][4];
#pragma unroll
            for (int mt = 0; mt < 2; mt++) {
                int r0 = wm + mt * 16 + g;
                tf32_split(As[stage][r0][k0 + t],         afh[mt][0], afl[mt][0]);
                tf32_split(As[stage][r0 + 8][k0 + t],     afh[mt][1], afl[mt][1]);
                tf32_split(As[stage][r0][k0 + t + 4],     afh[mt][2], afl[mt][2]);
                tf32_split(As[stage][r0 + 8][k0 + t + 4], afh[mt][3], afl[mt][3]);
            }
#pragma unroll
            for (int nt = 0; nt < 8; nt++) {
                uint32_t bh0, bl0, bh1, bl1;
                tf32_split(Bs[stage][k0 + t][wn + nt * 8 + g],     bh0, bl0);
                tf32_split(Bs[stage][k0 + t + 4][wn + nt * 8 + g], bh1, bl1);
#pragma unroll
                for (int mt = 0; mt < 2; mt++) {
                    MMA_TF32(acc[mt][nt], afl[mt][0], afl[mt][1], afl[mt][2], afl[mt][3], bh0, bh1);
                    MMA_TF32(acc[mt][nt], afh[mt][0], afh[mt][1], afh[mt][2], afh[mt][3], bl0, bl1);
                    MMA_TF32(acc[mt][nt], afh[mt][0], afh[mt][1], afh[mt][2], afh[mt][3], bh0, bh1);
                }
            }
        }
        __syncthreads();
    }

    // epilogue
#pragma unroll
    for (int mt = 0; mt < 2; mt++) {
        int r0 = m_base + wm + mt * 16 + g;
        int r1 = r0 + 8;
#pragma unroll
        for (int nt = 0; nt < 8; nt++) {
            int c = n_base + wn + nt * 8 + 2 * t;
            float b0 = 0.f, b1 = 0.f;
            if (bias) { b0 = bias[c]; b1 = bias[c + 1]; }
            if (r0 < M) {
                float2 v0 = make_float2(acc[mt][nt][0] + b0, acc[mt][nt][1] + b1);
                *(float2*)(C + (size_t)r0 * N + c) = v0;
            }
            if (r1 < M) {
                float2 v1 = make_float2(acc[mt][nt][2] + b0, acc[mt][nt][3] + b1);
                *(float2*)(C + (size_t)r1 * N + c) = v1;
            }
        }
    }
}

// ---------------- graph kernels ----------------
__global__ void reset_softmax_kernel(unsigned* mkey, float* dsum, int n) {
    int i = blockIdx.x * blockDim.x + threadIdx.x;
    if (i < n) { mkey[i] = NEG_INF_KEY; dsum[i] = 0.f; }
}

__global__ void fill_u32_kernel(unsigned* p, unsigned val, int n) {
    int i = blockIdx.x * blockDim.x + threadIdx.x;
    if (i < n) p[i] = val;
}

// one warp per edge: score = dot(q[dst], k[src]) * scale ; atomicMax into mkey
__global__ void trans_score_kernel(
    const float* __restrict__ q, const float* __restrict__ k,
    const int* __restrict__ src, const int* __restrict__ dst,
    float* __restrict__ score, unsigned* __restrict__ mkey, int E, float scale)
{
    int idx = blockIdx.x * blockDim.x + threadIdx.x;
    int e = idx >> 5, lane = idx & 31;
    if (e >= E) return;
    int d = dst[e], s0 = src[e];
    float4 qv = *(const float4*)(q + (size_t)d * DIMF + lane * 4);
    float4 kv = *(const float4*)(k + (size_t)s0 * DIMF + lane * 4);
    float s = qv.x * kv.x + qv.y * kv.y + qv.z * kv.z + qv.w * kv.w;
#pragma unroll
    for (int o = 16; o; o >>= 1) s += __shfl_xor_sync(0xffffffffu, s, o);
    if (lane == 0) {
        s *= scale;
        score[e] = s;
        atomicMax(mkey + d, fkey(s));
    }
}

// one warp per node: out[n] = dot(h[n,:], avec)
__global__ void node_dot_kernel(const float* __restrict__ h, const float* __restrict__ avec,
                                float* __restrict__ out, int n)
{
    int idx = blockIdx.x * blockDim.x + threadIdx.x;
    int i = idx >> 5, lane = idx & 31;
    if (i >= n) return;
    float4 hv = *(const float4*)(h + (size_t)i * DIMF + lane * 4);
    float4 av = *(const float4*)(avec + lane * 4);
    float s = hv.x * av.x + hv.y * av.y + hv.z * av.z + hv.w * av.w;
#pragma unroll
    for (int o = 16; o; o >>= 1) s += __shfl_xor_sync(0xffffffffu, s, o);
    if (lane == 0) out[i] = s;
}

__global__ void gat_score_kernel(const float* __restrict__ ss, const float* __restrict__ sd,
                                 const int* __restrict__ src, const int* __restrict__ dst,
                                 float* __restrict__ score, unsigned* __restrict__ mkey, int E)
{
    int e = blockIdx.x * blockDim.x + threadIdx.x;
    if (e >= E) return;
    float s = ss[src[e]] + sd[dst[e]];
    s = (s > 0.f) ? s : 0.2f * s;
    score[e] = s;
    atomicMax(mkey + dst[e], fkey(s));
}

__global__ void expsum_kernel(float* __restrict__ score, const unsigned* __restrict__ mkey,
                              float* __restrict__ dsum, const int* __restrict__ dst, int E)
{
    int e = blockIdx.x * blockDim.x + threadIdx.x;
    if (e >= E) return;
    int d = dst[e];
    float m = fdecode(mkey[d]);
    if (!isfinite(m)) m = 0.f;
    float ex = expf(score[e] - m);
    score[e] = ex;
    atomicAdd(dsum + d, ex);
}

// one warp per edge: out[dst,:] += (score[e]/dsum[dst]) * v[src,:]
__global__ void aggregate_kernel(const float* __restrict__ score, const float* __restrict__ dsum,
                                 const float* __restrict__ v,
                                 const int* __restrict__ src, const int* __restrict__ dst,
                                 float* __restrict__ out, int E)
{
    int idx = blockIdx.x * blockDim.x + threadIdx.x;
    int e = idx >> 5, lane = idx & 31;
    if (e >= E) return;
    int d = dst[e], s0 = src[e];
    float w = score[e] / (dsum[d] + 1e-16f);
    float4 vv = *(const float4*)(v + (size_t)s0 * DIMF + lane * 4);
    float* op = out + (size_t)d * DIMF + lane * 4;
    atomicAdd(op + 0, w * vv.x);
    atomicAdd(op + 1, w * vv.y);
    atomicAdd(op + 2, w * vv.z);
    atomicAdd(op + 3, w * vv.w);
}

__global__ void bias_add_kernel(float* __restrict__ out, const float* __restrict__ b, int n) {
    int i = blockIdx.x * blockDim.x + threadIdx.x;   // n*32 float4 slots
    if (i >= n * 32) return;
    int f = (i & 31) * 4;
    float4 bv = *(const float4*)(b + f);
    float4 ov = *(float4*)(out + (size_t)i * 4);
    ov.x += bv.x; ov.y += bv.y; ov.z += bv.z; ov.w += bv.w;
    *(float4*)(out + (size_t)i * 4) = ov;
}

// one warp per edge: H[e,:] = relu(P[dst] - Q[dst] + Q[src] + b1)   (512 wide)
__global__ void edge_h_kernel(const float* __restrict__ P, const float* __restrict__ Q,
                              const float* __restrict__ b1,
                              const int* __restrict__ src, const int* __restrict__ dst,
                              float* __restrict__ H, int E)
{
    int idx = blockIdx.x * blockDim.x + threadIdx.x;
    int e = idx >> 5, lane = idx & 31;
    if (e >= E) return;
    int d = dst[e], s0 = src[e];
    const float* Pd = P + (size_t)d * 512;
    const float* Qd = Q + (size_t)d * 512;
    const float* Qs = Q + (size_t)s0 * 512;
    float* He = H + (size_t)e * 512;
#pragma unroll
    for (int tt = 0; tt < 4; tt++) {
        int c = tt * 128 + lane * 4;
        float4 p  = *(const float4*)(Pd + c);
        float4 qd = *(const float4*)(Qd + c);
        float4 qs = *(const float4*)(Qs + c);
        float4 bb = *(const float4*)(b1 + c);
        float4 h;
        h.x = fmaxf(p.x - qd.x + qs.x + bb.x, 0.f);
        h.y = fmaxf(p.y - qd.y + qs.y + bb.y, 0.f);
        h.z = fmaxf(p.z - qd.z + qs.z + bb.z, 0.f);
        h.w = fmaxf(p.w - qd.w + qs.w + bb.w, 0.f);
        *(float4*)(He + c) = h;
    }
}

// one warp per edge: emax[dst,f] = max(emax, M[e,f]) via monotone-uint atomicMax
__global__ void scatter_max_kernel(const float* __restrict__ Mb, const int* __restrict__ dst,
                                   unsigned* __restrict__ emax, int E)
{
    int idx = blockIdx.x * blockDim.x + threadIdx.x;
    int e = idx >> 5, lane = idx & 31;
    if (e >= E) return;
    int d = dst[e];
    float4 mv = *(const float4*)(Mb + (size_t)e * DIMF + lane * 4);
    unsigned* ep = emax + (size_t)d * DIMF + lane * 4;
    atomicMax(ep + 0, fkey(mv.x));
    atomicMax(ep + 1, fkey(mv.y));
    atomicMax(ep + 2, fkey(mv.z));
    atomicMax(ep + 3, fkey(mv.w));
}

__global__ void finalize_max_kernel(const unsigned* __restrict__ emax, float* __restrict__ out, int total) {
    int i = blockIdx.x * blockDim.x + threadIdx.x;
    if (i >= total) return;
    float v = fdecode(emax[i]);
    out[i] = isfinite(v) ? v : 0.f;
}

// ---------------- host orchestration ----------------
static inline int div_up(int a, int b) { return (a + b - 1) / b; }

static void sgemm(const float* A, const float* B, const float* bias, float* C, int M, int N, int K) {
    dim3 grid(N / 128, div_up(M, 128));
    size_t shmem = SMEM_FLOATS * sizeof(float);
    mma3_sgemm_kernel<<<grid, 256, shmem>>>(A, B, bias, C, M, N, K);
}

struct Scratch {
    float *xl, *xp, *la, *pa, *q, *k, *v, *hs, *hd, *ss, *sd, *escore, *dsum, *P, *Q, *H, *M;
    unsigned *mkey, *emax;
};

static void run_trans(const Scratch& S, const float* x, int n,
                      const int* src, const int* dst, int E,
                      const float* Wq, const float* bq, const float* Wk, const float* bk,
                      const float* Wv, const float* bv, const float* Ws, const float* bs,
                      float* out)
{
    sgemm(x, Ws, bs, out, n, DIMF, DIMF);           // skip: out = x@Ws + bs
    sgemm(x, Wq, bq, S.q, n, DIMF, DIMF);
    sgemm(x, Wk, bk, S.k, n, DIMF, DIMF);
    sgemm(x, Wv, bv, S.v, n, DIMF, DIMF);
    reset_softmax_kernel<<<div_up(n, 256), 256>>>(S.mkey, S.dsum, n);
    float scale = 1.f / sqrtf((float)DIMF);
    trans_score_kernel<<<div_up(E * 32, 256), 256>>>(S.q, S.k, src, dst, S.escore, S.mkey, E, scale);
    expsum_kernel<<<div_up(E, 256), 256>>>(S.escore, S.mkey, S.dsum, dst, E);
    aggregate_kernel<<<div_up(E * 32, 256), 256>>>(S.escore, S.dsum, S.v, src, dst, out, E);
}

static void run_gat(const Scratch& S, const float* xs, int ns, const float* xd, int nd,
                    const int* src, const int* dst, int E,
                    const float* W, const float* a_src, const float* a_dst, const float* b,
                    float* out)   // accumulates into out
{
    sgemm(xs, W, nullptr, S.hs, ns, DIMF, DIMF);
    sgemm(xd, W, nullptr, S.hd, nd, DIMF, DIMF);
    node_dot_kernel<<<div_up(ns * 32, 256), 256>>>(S.hs, a_src, S.ss, ns);
    node_dot_kernel<<<div_up(nd * 32, 256), 256>>>(S.hd, a_dst, S.sd, nd);
    reset_softmax_kernel<<<div_up(nd, 256), 256>>>(S.mkey, S.dsum, nd);
    gat_score_kernel<<<div_up(E, 256), 256>>>(S.ss, S.sd, src, dst, S.escore, S.mkey, E);
    expsum_kernel<<<div_up(E, 256), 256>>>(S.escore, S.mkey, S.dsum, dst, E);
    aggregate_kernel<<<div_up(E * 32, 256), 256>>>(S.escore, S.dsum, S.hs, src, dst, out, E);
    bias_add_kernel<<<div_up(nd * 32, 256), 256>>>(out, b, nd);
}

static void run_edge(const Scratch& S, const float* x, int n,
                     const int* src, const int* dst, int E,
                     const float* W1, const float* b1, const float* W2, const float* b2,
                     float* out)   // stores out (overwrite)
{
    const float* W1a = W1;              // first 128 rows  (applies to x_i)
    const float* W1b = W1 + 128 * 512;  // second 128 rows (applies to x_j - x_i)
    sgemm(x, W1a, nullptr, S.P, n, 512, DIMF);
    sgemm(x, W1b, nullptr, S.Q, n, 512, DIMF);
    edge_h_kernel<<<div_up(E * 32, 256), 256>>>(S.P, S.Q, b1, src, dst, S.H, E);
    sgemm(S.H, W2, b2, S.M, E, DIMF, 512);
    fill_u32_kernel<<<div_up(n * DIMF, 256), 256>>>(S.emax, NEG_INF_KEY, n * DIMF);
    scatter_max_kernel<<<div_up(E * 32, 256), 256>>>(S.M, dst, S.emax, E);
    finalize_max_kernel<<<div_up(n * DIMF, 256), 256>>>(S.emax, out, n * DIMF);
}

extern "C" void kernel_launch(void* const* d_in, const int* in_sizes, int n_in,
                              void* d_out, int out_size)
{
    const float* x_lego  = (const float*)d_in[0];
    const float* x_point = (const float*)d_in[1];
    const float* tWq = (const float*)d_in[2];
    const float* tbq = (const float*)d_in[3];
    const float* tWk = (const float*)d_in[4];
    const float* tbk = (const float*)d_in[5];
    const float* tWv = (const float*)d_in[6];
    const float* tbv = (const float*)d_in[7];
    const float* tWs = (const float*)d_in[8];
    const float* tbs = (const float*)d_in[9];
    const float* eW1 = (const float*)d_in[10];
    const float* eb1 = (const float*)d_in[11];
    const float* eW2 = (const float*)d_in[12];
    const float* eb2 = (const float*)d_in[13];
    const float* gW  = (const float*)d_in[14];
    const float* gAs = (const float*)d_in[15];
    const float* gAd = (const float*)d_in[16];
    const float* gb  = (const float*)d_in[17];
    const int* ll_src = (const int*)d_in[18];
    const int* ll_dst = (const int*)d_in[19];
    const int* pp_src = (const int*)d_in[20];
    const int* pp_dst = (const int*)d_in[21];
    const int* lp_src = (const int*)d_in[22];
    const int* lp_dst = (const int*)d_in[23];
    const int* pl_src = (const int*)d_in[24];
    const int* pl_dst = (const int*)d_in[25];

    // allow >48KB dynamic smem for the GEMM kernel (idempotent host-side call)
    cudaFuncSetAttribute(mma3_sgemm_kernel, cudaFuncAttributeMaxDynamicSharedMemorySize,
                         SMEM_FLOATS * sizeof(float));

    Scratch S;
    cudaGetSymbolAddress((void**)&S.xl, g_xl);
    cudaGetSymbolAddress((void**)&S.xp, g_xp);
    cudaGetSymbolAddress((void**)&S.la, g_la);
    cudaGetSymbolAddress((void**)&S.pa, g_pa);
    cudaGetSymbolAddress((void**)&S.q,  g_q);
    cudaGetSymbolAddress((void**)&S.k,  g_k);
    cudaGetSymbolAddress((void**)&S.v,  g_v);
    cudaGetSymbolAddress((void**)&S.hs, g_hs);
    cudaGetSymbolAddress((void**)&S.hd, g_hd);
    cudaGetSymbolAddress((void**)&S.ss, g_ss);
    cudaGetSymbolAddress((void**)&S.sd, g_sd);
    cudaGetSymbolAddress((void**)&S.escore, g_escore);
    cudaGetSymbolAddress((void**)&S.dsum, g_dsum);
    cudaGetSymbolAddress((void**)&S.P, g_P);
    cudaGetSymbolAddress((void**)&S.Q, g_Q);
    cudaGetSymbolAddress((void**)&S.H, g_H);
    cudaGetSymbolAddress((void**)&S.M, g_M);
    cudaGetSymbolAddress((void**)&S.mkey, g_mkey);
    cudaGetSymbolAddress((void**)&S.emax, g_emax);

    cudaMemcpyAsync(S.xl, x_lego,  (size_t)N_LEGO * DIMF * sizeof(float),  cudaMemcpyDeviceToDevice);
    cudaMemcpyAsync(S.xp, x_point, (size_t)N_POINT * DIMF * sizeof(float), cudaMemcpyDeviceToDevice);

    for (int layer = 0; layer < 2; layer++) {
        int iA = 2 * layer, iB = 2 * layer + 1;
        int i_lp = 2 * layer, i_pl = 2 * layer + 1;

        // ---- conv A: lego_a = trans(x_lego) + gat(point->lego) ----
        run_trans(S, S.xl, N_LEGO, ll_src, ll_dst, NE_LL,
                  tWq + iA * DIMF * DIMF, tbq + iA * DIMF,
                  tWk + iA * DIMF * DIMF, tbk + iA * DIMF,
                  tWv + iA * DIMF * DIMF, tbv + iA * DIMF,
                  tWs + iA * DIMF * DIMF, tbs + iA * DIMF,
                  S.la);
        run_gat(S, S.xp, N_POINT, S.xl, N_LEGO, pl_src, pl_dst, NE_PL,
                gW + i_pl * DIMF * DIMF, gAs + i_pl * DIMF, gAd + i_pl * DIMF, gb + i_pl * DIMF,
                S.la);

        // ---- conv A: point_a = edge(x_point) + gat(lego->point) ----
        run_edge(S, S.xp, N_POINT, pp_src, pp_dst, NE_PP,
                 eW1 + (size_t)iA * 256 * 512, eb1 + iA * 512,
                 eW2 + (size_t)iA * 512 * DIMF, eb2 + iA * DIMF,
                 S.pa);
        run_gat(S, S.xl, N_LEGO, S.xp, N_POINT, lp_src, lp_dst, NE_LP,
                gW + i_lp * DIMF * DIMF, gAs + i_lp * DIMF, gAd + i_lp * DIMF, gb + i_lp * DIMF,
                S.pa);

        // ---- conv B: x_lego = trans(lego_a); x_point = edge(point_a) ----
        run_trans(S, S.la, N_LEGO, ll_src, ll_dst, NE_LL,
                  tWq + iB * DIMF * DIMF, tbq + iB * DIMF,
                  tWk + iB * DIMF * DIMF, tbk + iB * DIMF,
                  tWv + iB * DIMF * DIMF, tbv + iB * DIMF,
                  tWs + iB * DIMF * DIMF, tbs + iB * DIMF,
                  S.xl);
        run_edge(S, S.pa, N_POINT, pp_src, pp_dst, NE_PP,
                 eW1 + (size_t)iB * 256 * 512, eb1 + iB * 512,
                 eW2 + (size_t)iB * 512 * DIMF, eb2 + iB * DIMF,
                 S.xp);
    }

    float* out = (float*)d_out;
    cudaMemcpyAsync(out, S.xl, (size_t)N_LEGO * DIMF * sizeof(float), cudaMemcpyDeviceToDevice);
    cudaMemcpyAsync(out + (size_t)N_LEGO * DIMF, S.xp, (size_t)N_POINT * DIMF * sizeof(float),
                    cudaMemcpyDeviceToDevice);
}

// round 4
// speedup vs baseline: 1.3798x; 1.1064x over previous
#include <cuda_runtime.h>
#include <math.h>
#include <stdint.h>

#define DIMF 128
#define N_LEGO 50000
#define N_POINT 100000
#define NE_LL 500000
#define NE_PP 400000
#define NE_LP 500000
#define NE_PL 500000
#define NEG_INF_KEY 0x007FFFFFu

// ---------------- scratch (static device allocations; no cudaMalloc) ----------------
__device__ float    g_xl[N_LEGO * DIMF];
__device__ float    g_xp[N_POINT * DIMF];
__device__ float    g_la[N_LEGO * DIMF];
__device__ float    g_pa[N_POINT * DIMF];
__device__ float    g_q[N_LEGO * DIMF];
__device__ float    g_k[N_LEGO * DIMF];
__device__ float    g_v[N_LEGO * DIMF];
__device__ float    g_hs[N_POINT * DIMF];
__device__ float    g_hd[N_POINT * DIMF];
__device__ float    g_ss[N_POINT];
__device__ float    g_sd[N_POINT];
__device__ float    g_escore[NE_LL];
__device__ unsigned g_mkey[N_POINT];
__device__ float    g_dsum[N_POINT];
__device__ float    g_P[N_POINT * 512];
__device__ float    g_Q[N_POINT * 512];
__device__ unsigned g_emax[N_POINT * DIMF];

// ---------------- helpers ----------------
__device__ __forceinline__ unsigned fkey(float f) {
    unsigned u = __float_as_uint(f);
    return (u & 0x80000000u) ? ~u : (u | 0x80000000u);
}
__device__ __forceinline__ float fdecode(unsigned kk) {
    unsigned u = (kk & 0x80000000u) ? (kk ^ 0x80000000u) : ~kk;
    return __uint_as_float(u);
}
__device__ __forceinline__ float to_tf32(float x) {
    float r;
    asm("cvt.rna.tf32.f32 %0, %1;" : "=f"(r) : "f"(x));
    return r;
}
__device__ __forceinline__ void tf32_split(float v, uint32_t& hi, uint32_t& lo) {
    float h = to_tf32(v);
    float l = to_tf32(v - h);
    hi = __float_as_uint(h);
    lo = __float_as_uint(l);
}
__device__ __forceinline__ void cp_async16(void* dst, const void* src, int bytes) {
    uint32_t d = (uint32_t)__cvta_generic_to_shared(dst);
    asm volatile("cp.async.ca.shared.global [%0], [%1], 16, %2;\n"
                 :: "r"(d), "l"(src), "r"(bytes));
}

// ---------------- shared GEMM tiling constants ----------------
#define BM 128
#define BN 128
#define BK 32
#define AS_STRIDE 36     // As[m][k] : [128][36]  -> a-frag banks 4g+t (conflict-free)
#define BS_STRIDE 136    // Bs[k][n] : [32][136]  -> b-frag banks 8t+g (conflict-free)
#define SMEM_FLOATS (2 * BM * AS_STRIDE + 2 * BK * BS_STRIDE)
#define EDGE_SMEM_BYTES (SMEM_FLOATS * sizeof(float) + 2 * BM * sizeof(int))

#define MMA_TF32(accv, a0, a1, a2, a3, b0, b1)                                     \
    asm("mma.sync.aligned.m16n8k8.row.col.f32.tf32.tf32.f32 "                      \
        "{%0,%1,%2,%3}, {%4,%5,%6,%7}, {%8,%9}, {%0,%1,%2,%3};"                    \
        : "+f"(accv[0]), "+f"(accv[1]), "+f"(accv[2]), "+f"(accv[3])               \
        : "r"(a0), "r"(a1), "r"(a2), "r"(a3), "r"(b0), "r"(b1))

// 3xTF32 inner compute over one smem stage (shared by both GEMM kernels)
#define MMA_STAGE_COMPUTE(AsS, BsS)                                                \
    {                                                                              \
        _Pragma("unroll")                                                          \
        for (int ks = 0; ks < 4; ks++) {                                           \
            const int k0 = ks * 8;                                                 \
            uint32_t afh[2][4], afl[2][4];                                         \
            _Pragma("unroll")                                                      \
            for (int mt = 0; mt < 2; mt++) {                                       \
                int r0 = wm + mt * 16 + g;                                         \
                tf32_split(AsS[r0][k0 + t],         afh[mt][0], afl[mt][0]);       \
                tf32_split(AsS[r0 + 8][k0 + t],     afh[mt][1], afl[mt][1]);       \
                tf32_split(AsS[r0][k0 + t + 4],     afh[mt][2], afl[mt][2]);       \
                tf32_split(AsS[r0 + 8][k0 + t + 4], afh[mt][3], afl[mt][3]);       \
            }                                                                      \
            _Pragma("unroll")                                                      \
            for (int nt = 0; nt < 8; nt++) {                                       \
                uint32_t bh0, bl0, bh1, bl1;                                       \
                tf32_split(BsS[k0 + t][wn + nt * 8 + g],     bh0, bl0);            \
                tf32_split(BsS[k0 + t + 4][wn + nt * 8 + g], bh1, bl1);            \
                _Pragma("unroll")                                                  \
                for (int mt = 0; mt < 2; mt++) {                                   \
                    MMA_TF32(acc[mt][nt], afl[mt][0], afl[mt][1], afl[mt][2],      \
                             afl[mt][3], bh0, bh1);                                \
                    MMA_TF32(acc[mt][nt], afh[mt][0], afh[mt][1], afh[mt][2],      \
                             afh[mt][3], bl0, bl1);                                \
                    MMA_TF32(acc[mt][nt], afh[mt][0], afh[mt][1], afh[mt][2],      \
                             afh[mt][3], bh0, bh1);                                \
                }                                                                  \
            }                                                                      \
        }                                                                          \
    }

// ---------------- generic 3xTF32 GEMM: C[M,N] = A[M,K] @ B[K,N] (+bias) ----------------
__global__ __launch_bounds__(256, 2) void mma3_sgemm_kernel(
    const float* __restrict__ A, const float* __restrict__ B,
    const float* __restrict__ bias, float* __restrict__ C,
    int M, int N, int K)
{
    extern __shared__ float smem[];
    float (*As)[BM][AS_STRIDE] = (float (*)[BM][AS_STRIDE])smem;
    float (*Bs)[BK][BS_STRIDE] = (float (*)[BK][BS_STRIDE])(smem + 2 * BM * AS_STRIDE);

    const int tid  = threadIdx.x;
    const int warp = tid >> 5, lane = tid & 31;
    const int g = lane >> 2, t = lane & 3;
    const int warp_m = warp & 3, warp_n = warp >> 2;
    const int m_base = blockIdx.y * BM;
    const int n_base = blockIdx.x * BN;
    const int wm = warp_m * 32;
    const int wn = warp_n * 64;

    float acc[2][8][4];
#pragma unroll
    for (int i = 0; i < 2; i++)
#pragma unroll
        for (int j = 0; j < 8; j++)
#pragma unroll
            for (int c = 0; c < 4; c++) acc[i][j][c] = 0.f;

#define ISSUE_TILES(k0, st)                                                        \
    {                                                                              \
        _Pragma("unroll")                                                          \
        for (int i = 0; i < 4; i++) {                                              \
            int idx = tid + i * 256;                                               \
            int row = idx >> 3, c4 = (idx & 7) * 4;                                \
            int gr = m_base + row;                                                 \
            cp_async16(&As[st][row][c4], A + (size_t)gr * K + (k0) + c4,           \
                       (gr < M) ? 16 : 0);                                         \
        }                                                                          \
        _Pragma("unroll")                                                          \
        for (int i = 0; i < 4; i++) {                                              \
            int idx = tid + i * 256;                                               \
            int row = idx >> 5, c4 = (idx & 31) * 4;                               \
            cp_async16(&Bs[st][row][c4],                                           \
                       B + (size_t)((k0) + row) * N + n_base + c4, 16);            \
        }                                                                          \
        asm volatile("cp.async.commit_group;\n" ::);                               \
    }

    ISSUE_TILES(0, 0);

    int stage = 0;
    for (int kt = 0; kt < K; kt += BK, stage ^= 1) {
        const bool more = (kt + BK) < K;
        if (more) ISSUE_TILES(kt + BK, stage ^ 1);
        if (more) asm volatile("cp.async.wait_group 1;\n" ::);
        else      asm volatile("cp.async.wait_group 0;\n" ::);
        __syncthreads();
        MMA_STAGE_COMPUTE(As[stage], Bs[stage]);
        __syncthreads();
    }

    // epilogue
#pragma unroll
    for (int mt = 0; mt < 2; mt++) {
        int r0 = m_base + wm + mt * 16 + g;
        int r1 = r0 + 8;
#pragma unroll
        for (int nt = 0; nt < 8; nt++) {
            int c = n_base + wn + nt * 8 + 2 * t;
            float b0 = 0.f, b1 = 0.f;
            if (bias) { b0 = bias[c]; b1 = bias[c + 1]; }
            if (r0 < M) {
                float2 v0 = make_float2(acc[mt][nt][0] + b0, acc[mt][nt][1] + b1);
                *(float2*)(C + (size_t)r0 * N + c) = v0;
            }
            if (r1 < M) {
                float2 v1 = make_float2(acc[mt][nt][2] + b0, acc[mt][nt][3] + b1);
                *(float2*)(C + (size_t)r1 * N + c) = v1;
            }
        }
    }
}

// ---------------- fused EdgeConv MLP2 + segment-max GEMM ----------------
// A-tile built on the fly: A[e,k] = relu(P[dst[e],k] - Q[dst[e],k] + Q[src[e],k] + b1[k])
// C = A @ W2 (K=512, N=128), epilogue: atomicMax(emax[dst[e]*128 + c], fkey(C)).
// b2 is added later in finalize (max commutes with per-column constant).
__global__ __launch_bounds__(256, 2) void edge_fused_gemm_kernel(
    const float* __restrict__ P, const float* __restrict__ Q,
    const float* __restrict__ b1, const float* __restrict__ W2,
    const int* __restrict__ src, const int* __restrict__ dst,
    unsigned* __restrict__ emax, int E)
{
    extern __shared__ float smem[];
    float (*As)[BM][AS_STRIDE] = (float (*)[BM][AS_STRIDE])smem;
    float (*Bs)[BK][BS_STRIDE] = (float (*)[BK][BS_STRIDE])(smem + 2 * BM * AS_STRIDE);
    int* se = (int*)(smem + SMEM_FLOATS);
    int* de = se + BM;

    const int tid  = threadIdx.x;
    const int warp = tid >> 5, lane = tid & 31;
    const int g = lane >> 2, t = lane & 3;
    const int warp_m = warp & 3, warp_n = warp >> 2;
    const int e_base = blockIdx.y * BM;
    const int wm = warp_m * 32;
    const int wn = warp_n * 64;
    const int KTOT = 512;

    // load edge ids for this block (guarded; invalid rows -> node 0, masked at epilogue)
    if (tid < BM) {
        int e = e_base + tid;
        bool ok = (e < E);
        se[tid] = ok ? src[e] : 0;
        de[tid] = ok ? dst[e] : 0;
    }
    __syncthreads();

    float acc[2][8][4];
#pragma unroll
    for (int i = 0; i < 2; i++)
#pragma unroll
        for (int j = 0; j < 8; j++)
#pragma unroll
            for (int c = 0; c < 4; c++) acc[i][j][c] = 0.f;

#define ISSUE_B_W2(k0, st)                                                         \
    {                                                                              \
        _Pragma("unroll")                                                          \
        for (int i = 0; i < 4; i++) {                                              \
            int idx = tid + i * 256;                                               \
            int row = idx >> 5, c4 = (idx & 31) * 4;                               \
            cp_async16(&Bs[st][row][c4],                                           \
                       W2 + (size_t)((k0) + row) * 128 + c4, 16);                  \
        }                                                                          \
        asm volatile("cp.async.commit_group;\n" ::);                               \
    }

#define GATHER_A(k0, st)                                                           \
    {                                                                              \
        _Pragma("unroll")                                                          \
        for (int i = 0; i < 4; i++) {                                              \
            int idx = tid + i * 256;                                               \
            int row = idx >> 3, c4 = (idx & 7) * 4;                                \
            int s0 = se[row], d0 = de[row];                                        \
            float4 pv = *(const float4*)(P + (size_t)d0 * 512 + (k0) + c4);        \
            float4 qd = *(const float4*)(Q + (size_t)d0 * 512 + (k0) + c4);        \
            float4 qs = *(const float4*)(Q + (size_t)s0 * 512 + (k0) + c4);        \
            float4 bb = *(const float4*)(b1 + (k0) + c4);                          \
            As[st][row][c4 + 0] = fmaxf(pv.x - qd.x + qs.x + bb.x, 0.f);           \
            As[st][row][c4 + 1] = fmaxf(pv.y - qd.y + qs.y + bb.y, 0.f);           \
            As[st][row][c4 + 2] = fmaxf(pv.z - qd.z + qs.z + bb.z, 0.f);           \
            As[st][row][c4 + 3] = fmaxf(pv.w - qd.w + qs.w + bb.w, 0.f);           \
        }                                                                          \
    }

    GATHER_A(0, 0);
    ISSUE_B_W2(0, 0);

    int stage = 0;
    for (int kt = 0; kt < KTOT; kt += BK, stage ^= 1) {
        const bool more = (kt + BK) < KTOT;
        if (more) ISSUE_B_W2(kt + BK, stage ^ 1);
        if (more) asm volatile("cp.async.wait_group 1;\n" ::);
        else      asm volatile("cp.async.wait_group 0;\n" ::);
        __syncthreads();
        MMA_STAGE_COMPUTE(As[stage], Bs[stage]);
        // build next A stage while other buffer is live (no race: different stage)
        if (more) GATHER_A(kt + BK, stage ^ 1);
        __syncthreads();
    }

    // epilogue: segment-max via monotone-uint atomicMax
#pragma unroll
    for (int mt = 0; mt < 2; mt++) {
        int r0 = wm + mt * 16 + g;       // edge row within block
        int r1 = r0 + 8;
        int e0 = e_base + r0, e1 = e_base + r1;
        int d0 = de[r0], d1 = de[r1];
#pragma unroll
        for (int nt = 0; nt < 8; nt++) {
            int c = wn + nt * 8 + 2 * t;
            if (e0 < E) {
                atomicMax(emax + (size_t)d0 * DIMF + c,     fkey(acc[mt][nt][0]));
                atomicMax(emax + (size_t)d0 * DIMF + c + 1, fkey(acc[mt][nt][1]));
            }
            if (e1 < E) {
                atomicMax(emax + (size_t)d1 * DIMF + c,     fkey(acc[mt][nt][2]));
                atomicMax(emax + (size_t)d1 * DIMF + c + 1, fkey(acc[mt][nt][3]));
            }
        }
    }
}

// ---------------- graph kernels ----------------
__global__ void reset_softmax_kernel(unsigned* mkey, float* dsum, int n) {
    int i = blockIdx.x * blockDim.x + threadIdx.x;
    if (i < n) { mkey[i] = NEG_INF_KEY; dsum[i] = 0.f; }
}

__global__ void fill_u32_kernel(unsigned* p, unsigned val, int n) {
    int i = blockIdx.x * blockDim.x + threadIdx.x;
    if (i < n) p[i] = val;
}

// one warp per edge: score = dot(q[dst], k[src]) * scale ; atomicMax into mkey
__global__ void trans_score_kernel(
    const float* __restrict__ q, const float* __restrict__ k,
    const int* __restrict__ src, const int* __restrict__ dst,
    float* __restrict__ score, unsigned* __restrict__ mkey, int E, float scale)
{
    int idx = blockIdx.x * blockDim.x + threadIdx.x;
    int e = idx >> 5, lane = idx & 31;
    if (e >= E) return;
    int d = dst[e], s0 = src[e];
    float4 qv = *(const float4*)(q + (size_t)d * DIMF + lane * 4);
    float4 kv = *(const float4*)(k + (size_t)s0 * DIMF + lane * 4);
    float s = qv.x * kv.x + qv.y * kv.y + qv.z * kv.z + qv.w * kv.w;
#pragma unroll
    for (int o = 16; o; o >>= 1) s += __shfl_xor_sync(0xffffffffu, s, o);
    if (lane == 0) {
        s *= scale;
        score[e] = s;
        atomicMax(mkey + d, fkey(s));
    }
}

// one warp per node: out[n] = dot(h[n,:], avec)
__global__ void node_dot_kernel(const float* __restrict__ h, const float* __restrict__ avec,
                                float* __restrict__ out, int n)
{
    int idx = blockIdx.x * blockDim.x + threadIdx.x;
    int i = idx >> 5, lane = idx & 31;
    if (i >= n) return;
    float4 hv = *(const float4*)(h + (size_t)i * DIMF + lane * 4);
    float4 av = *(const float4*)(avec + lane * 4);
    float s = hv.x * av.x + hv.y * av.y + hv.z * av.z + hv.w * av.w;
#pragma unroll
    for (int o = 16; o; o >>= 1) s += __shfl_xor_sync(0xffffffffu, s, o);
    if (lane == 0) out[i] = s;
}

__global__ void gat_score_kernel(const float* __restrict__ ss, const float* __restrict__ sd,
                                 const int* __restrict__ src, const int* __restrict__ dst,
                                 float* __restrict__ score, unsigned* __restrict__ mkey, int E)
{
    int e = blockIdx.x * blockDim.x + threadIdx.x;
    if (e >= E) return;
    float s = ss[src[e]] + sd[dst[e]];
    s = (s > 0.f) ? s : 0.2f * s;
    score[e] = s;
    atomicMax(mkey + dst[e], fkey(s));
}

__global__ void expsum_kernel(float* __restrict__ score, const unsigned* __restrict__ mkey,
                              float* __restrict__ dsum, const int* __restrict__ dst, int E)
{
    int e = blockIdx.x * blockDim.x + threadIdx.x;
    if (e >= E) return;
    int d = dst[e];
    float m = fdecode(mkey[d]);
    if (!isfinite(m)) m = 0.f;
    float ex = expf(score[e] - m);
    score[e] = ex;
    atomicAdd(dsum + d, ex);
}

// one warp per edge: out[dst,:] += (score[e]/dsum[dst]) * v[src,:]
__global__ void aggregate_kernel(const float* __restrict__ score, const float* __restrict__ dsum,
                                 const float* __restrict__ v,
                                 const int* __restrict__ src, const int* __restrict__ dst,
                                 float* __restrict__ out, int E)
{
    int idx = blockIdx.x * blockDim.x + threadIdx.x;
    int e = idx >> 5, lane = idx & 31;
    if (e >= E) return;
    int d = dst[e], s0 = src[e];
    float w = score[e] / (dsum[d] + 1e-16f);
    float4 vv = *(const float4*)(v + (size_t)s0 * DIMF + lane * 4);
    float* op = out + (size_t)d * DIMF + lane * 4;
    atomicAdd(op + 0, w * vv.x);
    atomicAdd(op + 1, w * vv.y);
    atomicAdd(op + 2, w * vv.z);
    atomicAdd(op + 3, w * vv.w);
}

__global__ void bias_add_kernel(float* __restrict__ out, const float* __restrict__ b, int n) {
    int i = blockIdx.x * blockDim.x + threadIdx.x;   // n*32 float4 slots
    if (i >= n * 32) return;
    int f = (i & 31) * 4;
    float4 bv = *(const float4*)(b + f);
    float4 ov = *(float4*)(out + (size_t)i * 4);
    ov.x += bv.x; ov.y += bv.y; ov.z += bv.z; ov.w += bv.w;
    *(float4*)(out + (size_t)i * 4) = ov;
}

__global__ void finalize_max_b2_kernel(const unsigned* __restrict__ emax,
                                       const float* __restrict__ b2,
                                       float* __restrict__ out, int total) {
    int i = blockIdx.x * blockDim.x + threadIdx.x;
    if (i >= total) return;
    float v = fdecode(emax[i]);
    out[i] = isfinite(v) ? v + b2[i & (DIMF - 1)] : 0.f;
}

// ---------------- host orchestration ----------------
static inline int div_up(int a, int b) { return (a + b - 1) / b; }

static void sgemm(const float* A, const float* B, const float* bias, float* C, int M, int N, int K) {
    dim3 grid(N / 128, div_up(M, 128));
    size_t shmem = SMEM_FLOATS * sizeof(float);
    mma3_sgemm_kernel<<<grid, 256, shmem>>>(A, B, bias, C, M, N, K);
}

struct Scratch {
    float *xl, *xp, *la, *pa, *q, *k, *v, *hs, *hd, *ss, *sd, *escore, *dsum, *P, *Q;
    unsigned *mkey, *emax;
};

static void run_trans(const Scratch& S, const float* x, int n,
                      const int* src, const int* dst, int E,
                      const float* Wq, const float* bq, const float* Wk, const float* bk,
                      const float* Wv, const float* bv, const float* Ws, const float* bs,
                      float* out)
{
    sgemm(x, Ws, bs, out, n, DIMF, DIMF);           // skip: out = x@Ws + bs
    sgemm(x, Wq, bq, S.q, n, DIMF, DIMF);
    sgemm(x, Wk, bk, S.k, n, DIMF, DIMF);
    sgemm(x, Wv, bv, S.v, n, DIMF, DIMF);
    reset_softmax_kernel<<<div_up(n, 256), 256>>>(S.mkey, S.dsum, n);
    float scale = 1.f / sqrtf((float)DIMF);
    trans_score_kernel<<<div_up(E * 32, 256), 256>>>(S.q, S.k, src, dst, S.escore, S.mkey, E, scale);
    expsum_kernel<<<div_up(E, 256), 256>>>(S.escore, S.mkey, S.dsum, dst, E);
    aggregate_kernel<<<div_up(E * 32, 256), 256>>>(S.escore, S.dsum, S.v, src, dst, out, E);
}

static void run_gat(const Scratch& S, const float* xs, int ns, const float* xd, int nd,
                    const int* src, const int* dst, int E,
                    const float* W, const float* a_src, const float* a_dst, const float* b,
                    float* out)   // accumulates into out
{
    sgemm(xs, W, nullptr, S.hs, ns, DIMF, DIMF);
    sgemm(xd, W, nullptr, S.hd, nd, DIMF, DIMF);
    node_dot_kernel<<<div_up(ns * 32, 256), 256>>>(S.hs, a_src, S.ss, ns);
    node_dot_kernel<<<div_up(nd * 32, 256), 256>>>(S.hd, a_dst, S.sd, nd);
    reset_softmax_kernel<<<div_up(nd, 256), 256>>>(S.mkey, S.dsum, nd);
    gat_score_kernel<<<div_up(E, 256), 256>>>(S.ss, S.sd, src, dst, S.escore, S.mkey, E);
    expsum_kernel<<<div_up(E, 256), 256>>>(S.escore, S.mkey, S.dsum, dst, E);
    aggregate_kernel<<<div_up(E * 32, 256), 256>>>(S.escore, S.dsum, S.hs, src, dst, out, E);
    bias_add_kernel<<<div_up(nd * 32, 256), 256>>>(out, b, nd);
}

static void run_edge(const Scratch& S, const float* x, int n,
                     const int* src, const int* dst, int E,
                     const float* W1, const float* b1, const float* W2, const float* b2,
                     float* out)   // stores out (overwrite)
{
    const float* W1a = W1;              // first 128 rows  (applies to x_i)
    const float* W1b = W1 + 128 * 512;  // second 128 rows (applies to x_j - x_i)
    sgemm(x, W1a, nullptr, S.P, n, 512, DIMF);
    sgemm(x, W1b, nullptr, S.Q, n, 512, DIMF);
    fill_u32_kernel<<<div_up(n * DIMF, 256), 256>>>(S.emax, NEG_INF_KEY, n * DIMF);
    dim3 grid(1, div_up(E, BM));
    edge_fused_gemm_kernel<<<grid, 256, EDGE_SMEM_BYTES>>>(S.P, S.Q, b1, W2, src, dst, S.emax, E);
    finalize_max_b2_kernel<<<div_up(n * DIMF, 256), 256>>>(S.emax, b2, out, n * DIMF);
}

extern "C" void kernel_launch(void* const* d_in, const int* in_sizes, int n_in,
                              void* d_out, int out_size)
{
    const float* x_lego  = (const float*)d_in[0];
    const float* x_point = (const float*)d_in[1];
    const float* tWq = (const float*)d_in[2];
    const float* tbq = (const float*)d_in[3];
    const float* tWk = (const float*)d_in[4];
    const float* tbk = (const float*)d_in[5];
    const float* tWv = (const float*)d_in[6];
    const float* tbv = (const float*)d_in[7];
    const float* tWs = (const float*)d_in[8];
    const float* tbs = (const float*)d_in[9];
    const float* eW1 = (const float*)d_in[10];
    const float* eb1 = (const float*)d_in[11];
    const float* eW2 = (const float*)d_in[12];
    const float* eb2 = (const float*)d_in[13];
    const float* gW  = (const float*)d_in[14];
    const float* gAs = (const float*)d_in[15];
    const float* gAd = (const float*)d_in[16];
    const float* gb  = (const float*)d_in[17];
    const int* ll_src = (const int*)d_in[18];
    const int* ll_dst = (const int*)d_in[19];
    const int* pp_src = (const int*)d_in[20];
    const int* pp_dst = (const int*)d_in[21];
    const int* lp_src = (const int*)d_in[22];
    const int* lp_dst = (const int*)d_in[23];
    const int* pl_src = (const int*)d_in[24];
    const int* pl_dst = (const int*)d_in[25];

    // allow >48KB dynamic smem (idempotent host-side calls)
    cudaFuncSetAttribute(mma3_sgemm_kernel, cudaFuncAttributeMaxDynamicSharedMemorySize,
                         SMEM_FLOATS * sizeof(float));
    cudaFuncSetAttribute(edge_fused_gemm_kernel, cudaFuncAttributeMaxDynamicSharedMemorySize,
                         EDGE_SMEM_BYTES);

    Scratch S;
    cudaGetSymbolAddress((void**)&S.xl, g_xl);
    cudaGetSymbolAddress((void**)&S.xp, g_xp);
    cudaGetSymbolAddress((void**)&S.la, g_la);
    cudaGetSymbolAddress((void**)&S.pa, g_pa);
    cudaGetSymbolAddress((void**)&S.q,  g_q);
    cudaGetSymbolAddress((void**)&S.k,  g_k);
    cudaGetSymbolAddress((void**)&S.v,  g_v);
    cudaGetSymbolAddress((void**)&S.hs, g_hs);
    cudaGetSymbolAddress((void**)&S.hd, g_hd);
    cudaGetSymbolAddress((void**)&S.ss, g_ss);
    cudaGetSymbolAddress((void**)&S.sd, g_sd);
    cudaGetSymbolAddress((void**)&S.escore, g_escore);
    cudaGetSymbolAddress((void**)&S.dsum, g_dsum);
    cudaGetSymbolAddress((void**)&S.P, g_P);
    cudaGetSymbolAddress((void**)&S.Q, g_Q);
    cudaGetSymbolAddress((void**)&S.mkey, g_mkey);
    cudaGetSymbolAddress((void**)&S.emax, g_emax);

    cudaMemcpyAsync(S.xl, x_lego,  (size_t)N_LEGO * DIMF * sizeof(float),  cudaMemcpyDeviceToDevice);
    cudaMemcpyAsync(S.xp, x_point, (size_t)N_POINT * DIMF * sizeof(float), cudaMemcpyDeviceToDevice);

    for (int layer = 0; layer < 2; layer++) {
        int iA = 2 * layer, iB = 2 * layer + 1;
        int i_lp = 2 * layer, i_pl = 2 * layer + 1;

        // ---- conv A: lego_a = trans(x_lego) + gat(point->lego) ----
        run_trans(S, S.xl, N_LEGO, ll_src, ll_dst, NE_LL,
                  tWq + iA * DIMF * DIMF, tbq + iA * DIMF,
                  tWk + iA * DIMF * DIMF, tbk + iA * DIMF,
                  tWv + iA * DIMF * DIMF, tbv + iA * DIMF,
                  tWs + iA * DIMF * DIMF, tbs + iA * DIMF,
                  S.la);
        run_gat(S, S.xp, N_POINT, S.xl, N_LEGO, pl_src, pl_dst, NE_PL,
                gW + i_pl * DIMF * DIMF, gAs + i_pl * DIMF, gAd + i_pl * DIMF, gb + i_pl * DIMF,
                S.la);

        // ---- conv A: point_a = edge(x_point) + gat(lego->point) ----
        run_edge(S, S.xp, N_POINT, pp_src, pp_dst, NE_PP,
                 eW1 + (size_t)iA * 256 * 512, eb1 + iA * 512,
                 eW2 + (size_t)iA * 512 * DIMF, eb2 + iA * DIMF,
                 S.pa);
        run_gat(S, S.xl, N_LEGO, S.xp, N_POINT, lp_src, lp_dst, NE_LP,
                gW + i_lp * DIMF * DIMF, gAs + i_lp * DIMF, gAd + i_lp * DIMF, gb + i_lp * DIMF,
                S.pa);

        // ---- conv B: x_lego = trans(lego_a); x_point = edge(point_a) ----
        run_trans(S, S.la, N_LEGO, ll_src, ll_dst, NE_LL,
                  tWq + iB * DIMF * DIMF, tbq + iB * DIMF,
                  tWk + iB * DIMF * DIMF, tbk + iB * DIMF,
                  tWv + iB * DIMF * DIMF, tbv + iB * DIMF,
                  tWs + iB * DIMF * DIMF, tbs + iB * DIMF,
                  S.xl);
        run_edge(S, S.pa, N_POINT, pp_src, pp_dst, NE_PP,
                 eW1 + (size_t)iB * 256 * 512, eb1 + iB * 512,
                 eW2 + (size_t)iB * 512 * DIMF, eb2 + iB * DIMF,
                 S.xp);
    }

    float* out = (float*)d_out;
    cudaMemcpyAsync(out, S.xl, (size_t)N_LEGO * DIMF * sizeof(float), cudaMemcpyDeviceToDevice);
    cudaMemcpyAsync(out + (size_t)N_LEGO * DIMF, S.xp, (size_t)N_POINT * DIMF * sizeof(float),
                    cudaMemcpyDeviceToDevice);
}